// round 1
// baseline (speedup 1.0000x reference)
#include <cuda_runtime.h>
#include <math.h>

#define N_ROWS 32768
#define D_DIM  256
#define K_CODES 4096

// ---- output layout (floats) ----
#define OFF_LOSS  0ull
#define OFF_QST   1ull
#define OFF_PROBS (1ull + (unsigned long long)N_ROWS * D_DIM)                 // 8388609
#define OFF_PERP  (OFF_PROBS + (unsigned long long)N_ROWS * K_CODES)          // 142606337
#define OFF_IDX   (OFF_PERP + 1ull)                                           // 142606338
#define OFF_ACT   (OFF_IDX + N_ROWS)                                          // 142639106
#define OFF_USE   (OFF_ACT + 1ull)                                            // 142639107

// ---- scratch (static __device__: allocation-free) ----
static __device__ float g_wn[K_CODES * D_DIM];     // normalized codebook
static __device__ float g_xn[N_ROWS * D_DIM];      // normalized inputs
static __device__ float g_rowsum[N_ROWS];          // sum of exp(-d) per row (later: reciprocal)
static __device__ unsigned long long g_rowmin[N_ROWS]; // packed (dist_bits<<32 | k)
static __device__ float g_counts[K_CODES];
static __device__ float g_loss;

// --------------------------------------------------------------------------
__global__ void init_kernel() {
    int i = blockIdx.x * blockDim.x + threadIdx.x;
    if (i < N_ROWS) { g_rowsum[i] = 0.0f; g_rowmin[i] = 0xFFFFFFFFFFFFFFFFull; }
    if (i < K_CODES) g_counts[i] = 0.0f;
    if (i == 0) g_loss = 0.0f;
}

// one warp per row; D=256 => 8 floats/lane
__global__ void norm_kernel(const float* __restrict__ src, int rows, int which) {
    float* dst = which ? g_xn : g_wn;
    int warp = (blockIdx.x * blockDim.x + threadIdx.x) >> 5;
    int lane = threadIdx.x & 31;
    if (warp >= rows) return;
    const float4* s4 = reinterpret_cast<const float4*>(src + (size_t)warp * D_DIM);
    float4 a = s4[lane];
    float4 b = s4[lane + 32];
    float ss = a.x*a.x + a.y*a.y + a.z*a.z + a.w*a.w
             + b.x*b.x + b.y*b.y + b.z*b.z + b.w*b.w;
    #pragma unroll
    for (int o = 16; o; o >>= 1) ss += __shfl_xor_sync(0xffffffffu, ss, o);
    float sc = 1.0f / fmaxf(sqrtf(ss), 1e-12f);
    a.x *= sc; a.y *= sc; a.z *= sc; a.w *= sc;
    b.x *= sc; b.y *= sc; b.z *= sc; b.w *= sc;
    float4* d4 = reinterpret_cast<float4*>(dst + (size_t)warp * D_DIM);
    d4[lane] = a;
    d4[lane + 32] = b;
}

// --------------------------------------------------------------------------
// 128x128 tile over (rows n, codes k), BK=16 over d. 256 threads, 8x8/thread.
// Thread columns are kBase + j*16 + tx so scalar prob stores coalesce
// (OFF_PROBS is odd -> no vector stores possible into d_out).
__global__ __launch_bounds__(256) void gemm_kernel(float* __restrict__ out) {
    __shared__ __align__(16) float smem[2 * 16 * 128];   // 16 KB, reused in epilogue
    float* As = smem;             // [16][128]  (d-major)
    float* Bs = smem + 16 * 128;  // [16][128]

    const int tid = threadIdx.x;
    const int tx = tid & 15;
    const int ty = tid >> 4;
    const int nBase = blockIdx.y * 128;
    const int kBase = blockIdx.x * 128;

    float acc[8][8];
    #pragma unroll
    for (int i = 0; i < 8; i++)
        #pragma unroll
        for (int j = 0; j < 8; j++) acc[i][j] = 0.0f;

    for (int d0 = 0; d0 < D_DIM; d0 += 16) {
        #pragma unroll
        for (int q = 0; q < 2; q++) {
            int L = tid * 2 + q;
            int row = L >> 2;
            int c4 = (L & 3) << 2;
            float4 va = *reinterpret_cast<const float4*>(&g_xn[(size_t)(nBase + row) * D_DIM + d0 + c4]);
            As[(c4 + 0) * 128 + row] = va.x;
            As[(c4 + 1) * 128 + row] = va.y;
            As[(c4 + 2) * 128 + row] = va.z;
            As[(c4 + 3) * 128 + row] = va.w;
            float4 vb = *reinterpret_cast<const float4*>(&g_wn[(size_t)(kBase + row) * D_DIM + d0 + c4]);
            Bs[(c4 + 0) * 128 + row] = vb.x;
            Bs[(c4 + 1) * 128 + row] = vb.y;
            Bs[(c4 + 2) * 128 + row] = vb.z;
            Bs[(c4 + 3) * 128 + row] = vb.w;
        }
        __syncthreads();
        #pragma unroll
        for (int kk = 0; kk < 16; kk++) {
            float4 a0 = *reinterpret_cast<const float4*>(&As[kk * 128 + ty * 8]);
            float4 a1 = *reinterpret_cast<const float4*>(&As[kk * 128 + ty * 8 + 4]);
            float a[8] = {a0.x, a0.y, a0.z, a0.w, a1.x, a1.y, a1.z, a1.w};
            float b[8];
            #pragma unroll
            for (int j = 0; j < 8; j++) b[j] = Bs[kk * 128 + j * 16 + tx];
            #pragma unroll
            for (int i = 0; i < 8; i++)
                #pragma unroll
                for (int j = 0; j < 8; j++)
                    acc[i][j] = fmaf(a[i], b[j], acc[i][j]);
        }
        __syncthreads();
    }

    // ---- fused epilogue: exp(-dist), row sums, row argmin ----
    float* probs = out + OFF_PROBS;
    float rowSumLoc[8], rowMinLoc[8];
    int rowArgLoc[8];
    #pragma unroll
    for (int i = 0; i < 8; i++) {
        float s = 0.0f, mn = 1e30f;
        int ar = 0;
        float e[8];
        #pragma unroll
        for (int j = 0; j < 8; j++) {
            float dist = 2.0f - 2.0f * acc[i][j];
            float ev = __expf(-dist);
            e[j] = ev;
            s += ev;
            if (dist < mn) { mn = dist; ar = kBase + j * 16 + tx; }
        }
        size_t ro = (size_t)(nBase + ty * 8 + i) * K_CODES + kBase + tx;
        #pragma unroll
        for (int j = 0; j < 8; j++) probs[ro + j * 16] = e[j];
        rowSumLoc[i] = s;
        rowMinLoc[i] = mn;
        rowArgLoc[i] = ar;
    }

    // CTA-level row reductions in reused smem
    float* redS = smem;                         // [128][16]
    #pragma unroll
    for (int i = 0; i < 8; i++) redS[(ty * 8 + i) * 16 + tx] = rowSumLoc[i];
    __syncthreads();
    if (tid < 128) {
        float s = 0.0f;
        #pragma unroll
        for (int t = 0; t < 16; t++) s += redS[tid * 16 + t];
        atomicAdd(&g_rowsum[nBase + tid], s);
    }
    __syncthreads();
    unsigned long long* redM = reinterpret_cast<unsigned long long*>(smem); // [128][16]
    #pragma unroll
    for (int i = 0; i < 8; i++)
        redM[(ty * 8 + i) * 16 + tx] =
            (((unsigned long long)__float_as_uint(rowMinLoc[i])) << 32) |
            (unsigned long long)(unsigned)rowArgLoc[i];
    __syncthreads();
    if (tid < 128) {
        unsigned long long m = 0xFFFFFFFFFFFFFFFFull;
        #pragma unroll
        for (int t = 0; t < 16; t++) {
            unsigned long long v = redM[tid * 16 + t];
            m = (v < m) ? v : m;
        }
        atomicMin(&g_rowmin[nBase + tid], m);
    }
}

// --------------------------------------------------------------------------
// per-row: idx out, gather code row, counts, loss, invert rowsum
__global__ void finalize_kernel(float* __restrict__ out) {
    __shared__ float blockLoss;
    int lane = threadIdx.x & 31;
    int wid = threadIdx.x >> 5;
    if (threadIdx.x == 0) blockLoss = 0.0f;
    __syncthreads();
    int n = blockIdx.x * 8 + wid;
    unsigned long long packed = g_rowmin[n];
    int idx = (int)(unsigned)(packed & 0xFFFFFFFFull);
    float dmin = __uint_as_float((unsigned)(packed >> 32));
    if (lane == 0) {
        out[OFF_IDX + n] = (float)idx;
        atomicAdd(&g_counts[idx], 1.0f);
        g_rowsum[n] = 1.0f / g_rowsum[n];
        atomicAdd(&blockLoss, dmin);
    }
    const float* src = &g_wn[(size_t)idx * D_DIM];
    float* dst = &out[OFF_QST + (size_t)n * D_DIM];   // odd base: scalar, coalesced
    #pragma unroll
    for (int u = 0; u < 8; u++) dst[lane + u * 32] = src[lane + u * 32];
    __syncthreads();
    if (threadIdx.x == 0) atomicAdd(&g_loss, blockLoss);
}

// --------------------------------------------------------------------------
// probs[n,k] *= 1/rowsum[n]; probs base is odd -> float4 over +3-shifted region
__global__ void scale_kernel(float* __restrict__ out) {
    float* probs = out + OFF_PROBS;
    const size_t total = (size_t)N_ROWS * K_CODES;
    size_t gtid = (size_t)blockIdx.x * blockDim.x + threadIdx.x;
    if (gtid < 3) probs[gtid] *= g_rowsum[0];
    if (gtid == 3) probs[total - 1] *= g_rowsum[N_ROWS - 1];

    float4* p4 = reinterpret_cast<float4*>(probs + 3);
    const size_t total4 = (total - 3) / 4;   // 33554431
    const size_t stride = (size_t)gridDim.x * blockDim.x;
    for (size_t i = gtid; i < total4; i += stride) {
        size_t base = 3 + i * 4;
        float i0 = g_rowsum[(base + 0) >> 12];
        float i1 = g_rowsum[(base + 1) >> 12];
        float i2 = g_rowsum[(base + 2) >> 12];
        float i3 = g_rowsum[(base + 3) >> 12];
        float4 v = p4[i];
        v.x *= i0; v.y *= i1; v.z *= i2; v.w *= i3;
        p4[i] = v;
    }
}

// --------------------------------------------------------------------------
__global__ void scalars_kernel(float* __restrict__ out) {
    __shared__ float sEnt[256];
    __shared__ int sAct[256];
    int tid = threadIdx.x;
    float ent = 0.0f;
    int act = 0;
    for (int k = tid; k < K_CODES; k += 256) {
        float c = g_counts[k];
        float p = c * (1.0f / (float)N_ROWS);
        ent += p * logf(p + 1e-10f);
        act += (c > 0.0f) ? 1 : 0;
    }
    sEnt[tid] = ent;
    sAct[tid] = act;
    __syncthreads();
    for (int s = 128; s; s >>= 1) {
        if (tid < s) { sEnt[tid] += sEnt[tid + s]; sAct[tid] += sAct[tid + s]; }
        __syncthreads();
    }
    if (tid == 0) {
        out[OFF_LOSS] = 0.25f * g_loss / (float)((size_t)N_ROWS * D_DIM);
        out[OFF_PERP] = expf(-sEnt[0]);
        out[OFF_ACT]  = (float)sAct[0];
        out[OFF_USE]  = (float)sAct[0] * (100.0f / (float)K_CODES);
    }
}

// --------------------------------------------------------------------------
extern "C" void kernel_launch(void* const* d_in, const int* in_sizes, int n_in,
                              void* d_out, int out_size) {
    const float* inp = (const float*)d_in[0];   // (16,2048,256) fp32
    const float* w   = (const float*)d_in[1];   // (4096,256) fp32
    float* out = (float*)d_out;

    init_kernel<<<128, 256>>>();
    norm_kernel<<<K_CODES / 8, 256>>>(w, K_CODES, 0);
    norm_kernel<<<N_ROWS / 8, 256>>>(inp, N_ROWS, 1);
    gemm_kernel<<<dim3(K_CODES / 128, N_ROWS / 128), 256>>>(out);
    finalize_kernel<<<N_ROWS / 8, 256>>>(out);
    scale_kernel<<<4096, 256>>>(out);
    scalars_kernel<<<1, 256>>>(out);
}

// round 2
// speedup vs baseline: 1.0874x; 1.0874x over previous
#include <cuda_runtime.h>
#include <math.h>

#define N_ROWS 32768
#define D_DIM  256
#define K_CODES 4096

// ---- output layout (floats) ----
#define OFF_LOSS  0ull
#define OFF_QST   1ull
#define OFF_PROBS (1ull + (unsigned long long)N_ROWS * D_DIM)                 // 8388609
#define OFF_PERP  (OFF_PROBS + (unsigned long long)N_ROWS * K_CODES)          // 142606337
#define OFF_IDX   (OFF_PERP + 1ull)                                           // 142606338
#define OFF_ACT   (OFF_IDX + N_ROWS)                                          // 142639106
#define OFF_USE   (OFF_ACT + 1ull)                                            // 142639107

// ---- scratch (static __device__: allocation-free) ----
static __device__ float g_wn[K_CODES * D_DIM];     // normalized codebook
static __device__ float g_xn[N_ROWS * D_DIM];      // normalized inputs
static __device__ float g_rowsum[N_ROWS];          // sum of exp(-d) per row (later: reciprocal)
static __device__ unsigned long long g_rowmin[N_ROWS]; // packed (dist_bits<<32 | k)
static __device__ float g_counts[K_CODES];
static __device__ float g_loss;

// --------------------------------------------------------------------------
__global__ void init_kernel() {
    int i = blockIdx.x * blockDim.x + threadIdx.x;
    if (i < N_ROWS) { g_rowsum[i] = 0.0f; g_rowmin[i] = 0xFFFFFFFFFFFFFFFFull; }
    if (i < K_CODES) g_counts[i] = 0.0f;
    if (i == 0) g_loss = 0.0f;
}

// one warp per row; D=256 => 8 floats/lane
__global__ void norm_kernel(const float* __restrict__ src, int rows, int which) {
    float* dst = which ? g_xn : g_wn;
    int warp = (blockIdx.x * blockDim.x + threadIdx.x) >> 5;
    int lane = threadIdx.x & 31;
    if (warp >= rows) return;
    const float4* s4 = reinterpret_cast<const float4*>(src + (size_t)warp * D_DIM);
    float4 a = s4[lane];
    float4 b = s4[lane + 32];
    float ss = a.x*a.x + a.y*a.y + a.z*a.z + a.w*a.w
             + b.x*b.x + b.y*b.y + b.z*b.z + b.w*b.w;
    #pragma unroll
    for (int o = 16; o; o >>= 1) ss += __shfl_xor_sync(0xffffffffu, ss, o);
    float sc = 1.0f / fmaxf(sqrtf(ss), 1e-12f);
    a.x *= sc; a.y *= sc; a.z *= sc; a.w *= sc;
    b.x *= sc; b.y *= sc; b.z *= sc; b.w *= sc;
    float4* d4 = reinterpret_cast<float4*>(dst + (size_t)warp * D_DIM);
    d4[lane] = a;
    d4[lane + 32] = b;
}

// --------------------------------------------------------------------------
// 128x128 tile over (rows n, codes k), BK=16 over d. 256 threads.
// Micro-tile: 8 rows x 4 column-PAIRS per thread using packed fma.rn.f32x2.
// Thread columns: kBase + j*32 + 2*tx + {0,1}.
__global__ __launch_bounds__(256) void gemm_kernel(float* __restrict__ out) {
    __shared__ __align__(16) float smem[2 * 16 * 128];   // 16 KB, reused in epilogue
    float* As = smem;             // [16][128]  (d-major)
    float* Bs = smem + 16 * 128;  // [16][128]

    const int tid = threadIdx.x;
    const int tx = tid & 15;
    const int ty = tid >> 4;
    const int nBase = blockIdx.y * 128;
    const int kBase = blockIdx.x * 128;

    unsigned long long acc2[8][4];
    #pragma unroll
    for (int i = 0; i < 8; i++)
        #pragma unroll
        for (int j = 0; j < 4; j++) acc2[i][j] = 0ull;

    for (int d0 = 0; d0 < D_DIM; d0 += 16) {
        #pragma unroll
        for (int q = 0; q < 2; q++) {
            int L = tid * 2 + q;
            int row = L >> 2;
            int c4 = (L & 3) << 2;
            float4 va = *reinterpret_cast<const float4*>(&g_xn[(size_t)(nBase + row) * D_DIM + d0 + c4]);
            As[(c4 + 0) * 128 + row] = va.x;
            As[(c4 + 1) * 128 + row] = va.y;
            As[(c4 + 2) * 128 + row] = va.z;
            As[(c4 + 3) * 128 + row] = va.w;
            float4 vb = *reinterpret_cast<const float4*>(&g_wn[(size_t)(kBase + row) * D_DIM + d0 + c4]);
            Bs[(c4 + 0) * 128 + row] = vb.x;
            Bs[(c4 + 1) * 128 + row] = vb.y;
            Bs[(c4 + 2) * 128 + row] = vb.z;
            Bs[(c4 + 3) * 128 + row] = vb.w;
        }
        __syncthreads();
        #pragma unroll
        for (int kk = 0; kk < 16; kk++) {
            float4 a0 = *reinterpret_cast<const float4*>(&As[kk * 128 + ty * 8]);
            float4 a1 = *reinterpret_cast<const float4*>(&As[kk * 128 + ty * 8 + 4]);
            float a[8] = {a0.x, a0.y, a0.z, a0.w, a1.x, a1.y, a1.z, a1.w};
            unsigned long long ad[8];
            #pragma unroll
            for (int i = 0; i < 8; i++)
                asm("mov.b64 %0, {%1, %1};" : "=l"(ad[i]) : "f"(a[i]));
            unsigned long long b2[4];
            #pragma unroll
            for (int j = 0; j < 4; j++)
                b2[j] = *reinterpret_cast<const unsigned long long*>(&Bs[kk * 128 + j * 32 + 2 * tx]);
            #pragma unroll
            for (int i = 0; i < 8; i++)
                #pragma unroll
                for (int j = 0; j < 4; j++)
                    asm("fma.rn.f32x2 %0, %1, %2, %3;"
                        : "=l"(acc2[i][j]) : "l"(ad[i]), "l"(b2[j]), "l"(acc2[i][j]));
        }
        __syncthreads();
    }

    // ---- fused epilogue: exp(-dist), row sums, row argmin ----
    float* probs = out + OFF_PROBS;
    float rowSumLoc[8], rowMinLoc[8];
    int rowArgLoc[8];
    #pragma unroll
    for (int i = 0; i < 8; i++) {
        float s = 0.0f, mn = 1e30f;
        int ar = 0;
        float e[8];
        #pragma unroll
        for (int j = 0; j < 4; j++) {
            float lo, hi;
            asm("mov.b64 {%0, %1}, %2;" : "=f"(lo), "=f"(hi) : "l"(acc2[i][j]));
            float dist0 = 2.0f - 2.0f * lo;
            float dist1 = 2.0f - 2.0f * hi;
            float e0 = __expf(-dist0);
            float e1 = __expf(-dist1);
            e[j * 2 + 0] = e0;
            e[j * 2 + 1] = e1;
            s += e0 + e1;
            if (dist0 < mn) { mn = dist0; ar = kBase + j * 32 + 2 * tx; }
            if (dist1 < mn) { mn = dist1; ar = kBase + j * 32 + 2 * tx + 1; }
        }
        size_t ro = (size_t)(nBase + ty * 8 + i) * K_CODES + kBase + 2 * tx;
        #pragma unroll
        for (int j = 0; j < 4; j++) {
            probs[ro + j * 32 + 0] = e[j * 2 + 0];
            probs[ro + j * 32 + 1] = e[j * 2 + 1];
        }
        rowSumLoc[i] = s;
        rowMinLoc[i] = mn;
        rowArgLoc[i] = ar;
    }

    // CTA-level row reductions in reused smem
    float* redS = smem;                         // [128][16]
    #pragma unroll
    for (int i = 0; i < 8; i++) redS[(ty * 8 + i) * 16 + tx] = rowSumLoc[i];
    __syncthreads();
    if (tid < 128) {
        float s = 0.0f;
        #pragma unroll
        for (int t = 0; t < 16; t++) s += redS[tid * 16 + t];
        atomicAdd(&g_rowsum[nBase + tid], s);
    }
    __syncthreads();
    unsigned long long* redM = reinterpret_cast<unsigned long long*>(smem); // [128][16]
    #pragma unroll
    for (int i = 0; i < 8; i++)
        redM[(ty * 8 + i) * 16 + tx] =
            (((unsigned long long)__float_as_uint(rowMinLoc[i])) << 32) |
            (unsigned long long)(unsigned)rowArgLoc[i];
    __syncthreads();
    if (tid < 128) {
        unsigned long long m = 0xFFFFFFFFFFFFFFFFull;
        #pragma unroll
        for (int t = 0; t < 16; t++) {
            unsigned long long v = redM[tid * 16 + t];
            m = (v < m) ? v : m;
        }
        atomicMin(&g_rowmin[nBase + tid], m);
    }
}

// --------------------------------------------------------------------------
// per-row: idx out, gather code row, counts, loss, invert rowsum
__global__ void finalize_kernel(float* __restrict__ out) {
    __shared__ float blockLoss;
    int lane = threadIdx.x & 31;
    int wid = threadIdx.x >> 5;
    if (threadIdx.x == 0) blockLoss = 0.0f;
    __syncthreads();
    int n = blockIdx.x * 8 + wid;
    unsigned long long packed = g_rowmin[n];
    int idx = (int)(unsigned)(packed & 0xFFFFFFFFull);
    float dmin = __uint_as_float((unsigned)(packed >> 32));
    if (lane == 0) {
        out[OFF_IDX + n] = (float)idx;
        atomicAdd(&g_counts[idx], 1.0f);
        g_rowsum[n] = 1.0f / g_rowsum[n];
        atomicAdd(&blockLoss, dmin);
    }
    const float* src = &g_wn[(size_t)idx * D_DIM];
    float* dst = &out[OFF_QST + (size_t)n * D_DIM];   // odd base: scalar, coalesced
    #pragma unroll
    for (int u = 0; u < 8; u++) dst[lane + u * 32] = src[lane + u * 32];
    __syncthreads();
    if (threadIdx.x == 0) atomicAdd(&g_loss, blockLoss);
}

// --------------------------------------------------------------------------
// probs[n,k] *= 1/rowsum[n]; probs base is odd -> float4 over +3-shifted region
__global__ void scale_kernel(float* __restrict__ out) {
    float* probs = out + OFF_PROBS;
    const size_t total = (size_t)N_ROWS * K_CODES;
    size_t gtid = (size_t)blockIdx.x * blockDim.x + threadIdx.x;
    if (gtid < 3) probs[gtid] *= g_rowsum[0];
    if (gtid == 3) probs[total - 1] *= g_rowsum[N_ROWS - 1];

    float4* p4 = reinterpret_cast<float4*>(probs + 3);
    const size_t total4 = (total - 3) / 4;   // 33554431
    const size_t stride = (size_t)gridDim.x * blockDim.x;
    for (size_t i = gtid; i < total4; i += stride) {
        size_t base = 3 + i * 4;
        float i0 = g_rowsum[(base + 0) >> 12];
        float i1 = g_rowsum[(base + 1) >> 12];
        float i2 = g_rowsum[(base + 2) >> 12];
        float i3 = g_rowsum[(base + 3) >> 12];
        float4 v = p4[i];
        v.x *= i0; v.y *= i1; v.z *= i2; v.w *= i3;
        p4[i] = v;
    }
}

// --------------------------------------------------------------------------
__global__ void scalars_kernel(float* __restrict__ out) {
    __shared__ float sEnt[256];
    __shared__ int sAct[256];
    int tid = threadIdx.x;
    float ent = 0.0f;
    int act = 0;
    for (int k = tid; k < K_CODES; k += 256) {
        float c = g_counts[k];
        float p = c * (1.0f / (float)N_ROWS);
        ent += p * logf(p + 1e-10f);
        act += (c > 0.0f) ? 1 : 0;
    }
    sEnt[tid] = ent;
    sAct[tid] = act;
    __syncthreads();
    for (int s = 128; s; s >>= 1) {
        if (tid < s) { sEnt[tid] += sEnt[tid + s]; sAct[tid] += sAct[tid + s]; }
        __syncthreads();
    }
    if (tid == 0) {
        out[OFF_LOSS] = 0.25f * g_loss / (float)((size_t)N_ROWS * D_DIM);
        out[OFF_PERP] = expf(-sEnt[0]);
        out[OFF_ACT]  = (float)sAct[0];
        out[OFF_USE]  = (float)sAct[0] * (100.0f / (float)K_CODES);
    }
}

// --------------------------------------------------------------------------
extern "C" void kernel_launch(void* const* d_in, const int* in_sizes, int n_in,
                              void* d_out, int out_size) {
    const float* inp = (const float*)d_in[0];   // (16,2048,256) fp32
    const float* w   = (const float*)d_in[1];   // (4096,256) fp32
    float* out = (float*)d_out;

    init_kernel<<<128, 256>>>();
    norm_kernel<<<K_CODES / 8, 256>>>(w, K_CODES, 0);
    norm_kernel<<<N_ROWS / 8, 256>>>(inp, N_ROWS, 1);
    gemm_kernel<<<dim3(K_CODES / 128, N_ROWS / 128), 256>>>(out);
    finalize_kernel<<<N_ROWS / 8, 256>>>(out);
    scale_kernel<<<4096, 256>>>(out);
    scalars_kernel<<<1, 256>>>(out);
}